// round 17
// baseline (speedup 1.0000x reference)
#include <cuda_runtime.h>
#include <cstdint>

#define N_NODES 512
#define N_EDGES (512 * 512)
#define CHUNKS 256
#define EDGES_PER_CHUNK (N_EDGES / CHUNKS)   // 1024
#define NT 128
#define PGRID 592                             // 4 CTAs/SM * 148 SM, all resident

// ---------------- persistent device scratch (no allocations allowed) ---------
__device__ int   g_ptr[N_NODES + 1];
__device__ float g_invc[N_NODES];
__device__ int   g_counts[CHUNKS * N_NODES];
__device__ int   g_base[CHUNKS * N_NODES];
__device__ int   g_work[4];                   // per-layer work-stealing counters
__device__ __align__(16) float g_eas[(size_t)N_EDGES * 8];  // [ea0..5, src_bits, 0]
__device__ float g_bufA[N_NODES * 36];
__device__ float g_bufB[N_NODES * 36];

// ---------------- f32x2 packed helpers ---------------------------------------
__device__ __forceinline__ uint64_t f2pk(float lo, float hi) {
    uint64_t r; asm("mov.b64 %0, {%1,%2};" : "=l"(r) : "f"(lo), "f"(hi)); return r;
}
__device__ __forceinline__ void f2upk(uint64_t v, float& lo, float& hi) {
    asm("mov.b64 {%0,%1}, %2;" : "=f"(lo), "=f"(hi) : "l"(v));
}
__device__ __forceinline__ uint64_t f2fma(uint64_t a, uint64_t b, uint64_t c) {
    uint64_t d; asm("fma.rn.f32x2 %0, %1, %2, %3;" : "=l"(d) : "l"(a), "l"(b), "l"(c));
    return d;
}
__device__ __forceinline__ uint64_t f2relu(uint64_t v) {
    float lo, hi; f2upk(v, lo, hi);
    return f2pk(fmaxf(lo, 0.f), fmaxf(hi, 0.f));
}

// ---------------- CSR build (atomic-free in gmem) ----------------------------
__global__ __launch_bounds__(256) void count_kernel(const int* __restrict__ dst) {
    __shared__ int h[N_NODES];
    for (int n = threadIdx.x; n < N_NODES; n += 256) h[n] = 0;
    __syncthreads();
    const int base = blockIdx.x * EDGES_PER_CHUNK;
    for (int k = threadIdx.x; k < EDGES_PER_CHUNK; k += 256)
        atomicAdd(&h[dst[base + k]], 1);
    __syncthreads();
    for (int n = threadIdx.x; n < N_NODES; n += 256)
        g_counts[blockIdx.x * N_NODES + n] = h[n];
}

__global__ __launch_bounds__(N_NODES) void plan_kernel() {
    __shared__ int s[N_NODES];
    const int t = threadIdx.x;
    if (t < 4) g_work[t] = 0;                 // reset work-stealing counters
    int cnt = 0;
#pragma unroll 4
    for (int c = 0; c < CHUNKS; c++) cnt += g_counts[c * N_NODES + t];
    s[t] = cnt;
    __syncthreads();
    for (int off = 1; off < N_NODES; off <<= 1) {
        int v = (t >= off) ? s[t - off] : 0;
        __syncthreads();
        s[t] += v;
        __syncthreads();
    }
    const int incl = s[t];
    g_ptr[t + 1] = incl;
    if (t == 0) g_ptr[0] = 0;
    g_invc[t] = 1.0f / (float)max(cnt, 1);
    int run = incl - cnt;
#pragma unroll 4
    for (int c = 0; c < CHUNKS; c++) {
        int v = g_counts[c * N_NODES + t];
        g_base[c * N_NODES + t] = run;
        run += v;
    }
}

__global__ __launch_bounds__(256) void scatter_kernel(const int* __restrict__ srcv,
                                                      const int* __restrict__ dst,
                                                      const float* __restrict__ ea) {
    __shared__ int cur[N_NODES];
    for (int n = threadIdx.x; n < N_NODES; n += 256)
        cur[n] = g_base[blockIdx.x * N_NODES + n];
    __syncthreads();
    const int base = blockIdx.x * EDGES_PER_CHUNK;
    for (int k = threadIdx.x; k < EDGES_PER_CHUNK; k += 256) {
        const int e = base + k;
        const int p = atomicAdd(&cur[dst[e]], 1);
        const float2* er = (const float2*)(ea + (size_t)e * 6);
        const float2 e0 = __ldg(er + 0), e1 = __ldg(er + 1), e2 = __ldg(er + 2);
        float4* w = (float4*)(g_eas + (size_t)p * 8);
        w[0] = make_float4(e0.x, e0.y, e1.x, e1.y);
        w[1] = make_float4(e2.x, e2.y, __int_as_float(srcv[e]), 0.f);
    }
}

// ---------------- persistent NNConv layer: work-stealing (dst, slice) --------
// Full weights staged once per CTA; each work item = one (dst, channel-slice).
// Thread handles edge pair (k, k+NT) sharing every weight LDS (EB2).
template <int CIN, int COUT, int NSLICES, int SLICE, int SLICEP>
__global__ __launch_bounds__(NT) void layer_persist(
    const float* __restrict__ We,     // [6, CIN*COUT]
    const float* __restrict__ be,     // [CIN*COUT]
    const float* __restrict__ root,   // [CIN, COUT]
    const float* __restrict__ bias,   // [COUT]
    const float* __restrict__ hin,    // [N, CIN]
    float*       __restrict__ hout,   // [N, COUT]
    int widx)                         // work-counter index
{
    static_assert(SLICEP % 4 == 0, "pad");
    __shared__ __align__(16) float sWe[NSLICES * 6 * CIN * SLICEP];
    __shared__ __align__(16) float sBe[NSLICES * CIN * SLICEP];
    __shared__ float sacc[SLICEP];
    __shared__ int s_w;

    const int tid = threadIdx.x;

    // stage ALL slices' weights once per CTA (layout: [slice][v*CIN+i][oc])
    for (int t = tid; t < NSLICES * 6 * CIN * SLICEP; t += NT) {
        const int sl = t / (6 * CIN * SLICEP);
        const int r  = t % (6 * CIN * SLICEP);
        const int vi = r / SLICEP;
        const int oc = r % SLICEP;
        sWe[t] = (oc < SLICE) ? We[vi * COUT + sl * SLICE + oc] : 0.f;
    }
    for (int t = tid; t < NSLICES * CIN * SLICEP; t += NT) {
        const int sl = t / (CIN * SLICEP);
        const int r  = t % (CIN * SLICEP);
        const int i  = r / SLICEP;
        const int oc = r % SLICEP;
        sBe[t] = (oc < SLICE) ? be[i * COUT + sl * SLICE + oc] : 0.f;
    }

    for (;;) {
        if (tid == 0) s_w = atomicAdd(&g_work[widx], 1);
        __syncthreads();                       // also orders staging on iter 0
        const int w = s_w;
        if (w >= N_NODES * NSLICES) break;
        const int d  = w / NSLICES;
        const int sl = w % NSLICES;

        if (tid < SLICEP) sacc[tid] = 0.f;
        __syncthreads();

        const float* wBase = sWe + sl * 6 * CIN * SLICEP;
        const float* bBase = sBe + sl * CIN * SLICEP;
        const int start = g_ptr[d], finish = g_ptr[d + 1];

        uint64_t msgA[SLICEP / 2], msgB[SLICEP / 2];
#pragma unroll
        for (int p = 0; p < SLICEP / 2; p++) { msgA[p] = 0; msgB[p] = 0; }

        for (int k0 = start; k0 < finish; k0 += 2 * NT) {
            const int kA = k0 + tid;
            const int kB = kA + NT;
            const bool vA = (kA < finish);
            const bool vB = (kB < finish);
            const int iA = vA ? kA : start;    // clamped; invalid lane killed via x=0
            const int iB = vB ? kB : start;

            const float4 a0 = __ldg((const float4*)(g_eas + (size_t)iA * 8));
            const float4 a1 = __ldg((const float4*)(g_eas + (size_t)iA * 8 + 4));
            const float4 b0 = __ldg((const float4*)(g_eas + (size_t)iB * 8));
            const float4 b1 = __ldg((const float4*)(g_eas + (size_t)iB * 8 + 4));

            uint64_t apA[6], apB[6];
            apA[0] = f2pk(a0.x, a0.x); apA[1] = f2pk(a0.y, a0.y);
            apA[2] = f2pk(a0.z, a0.z); apA[3] = f2pk(a0.w, a0.w);
            apA[4] = f2pk(a1.x, a1.x); apA[5] = f2pk(a1.y, a1.y);
            apB[0] = f2pk(b0.x, b0.x); apB[1] = f2pk(b0.y, b0.y);
            apB[2] = f2pk(b0.z, b0.z); apB[3] = f2pk(b0.w, b0.w);
            apB[4] = f2pk(b1.x, b1.x); apB[5] = f2pk(b1.y, b1.y);

            const int sA = __float_as_int(a1.z);
            const int sB = __float_as_int(b1.z);
            const float* xrA = hin + sA * CIN;
            const float* xrB = hin + sB * CIN;

            auto body = [&](int i, float xiA, float xiB) {
                const uint64_t xpA = f2pk(xiA, xiA);
                const uint64_t xpB = f2pk(xiB, xiB);
                const ulonglong2* w0 = (const ulonglong2*)(wBase + (0 * CIN + i) * SLICEP);
                const ulonglong2* w1 = (const ulonglong2*)(wBase + (1 * CIN + i) * SLICEP);
                const ulonglong2* w2 = (const ulonglong2*)(wBase + (2 * CIN + i) * SLICEP);
                const ulonglong2* w3 = (const ulonglong2*)(wBase + (3 * CIN + i) * SLICEP);
                const ulonglong2* w4 = (const ulonglong2*)(wBase + (4 * CIN + i) * SLICEP);
                const ulonglong2* w5 = (const ulonglong2*)(wBase + (5 * CIN + i) * SLICEP);
                const ulonglong2* bb = (const ulonglong2*)(bBase + i * SLICEP);
#pragma unroll
                for (int c = 0; c < SLICEP / 4; c++) {
                    const ulonglong2 bi = bb[c];
                    const ulonglong2 q0 = w0[c], q1 = w1[c], q2 = w2[c],
                                     q3 = w3[c], q4 = w4[c], q5 = w5[c];
                    uint64_t tA0 = f2fma(apA[0], q0.x, bi.x);
                    tA0 = f2fma(apA[1], q1.x, tA0); tA0 = f2fma(apA[2], q2.x, tA0);
                    tA0 = f2fma(apA[3], q3.x, tA0); tA0 = f2fma(apA[4], q4.x, tA0);
                    tA0 = f2fma(apA[5], q5.x, tA0);
                    uint64_t tB0 = f2fma(apB[0], q0.x, bi.x);
                    tB0 = f2fma(apB[1], q1.x, tB0); tB0 = f2fma(apB[2], q2.x, tB0);
                    tB0 = f2fma(apB[3], q3.x, tB0); tB0 = f2fma(apB[4], q4.x, tB0);
                    tB0 = f2fma(apB[5], q5.x, tB0);
                    uint64_t tA1 = f2fma(apA[0], q0.y, bi.y);
                    tA1 = f2fma(apA[1], q1.y, tA1); tA1 = f2fma(apA[2], q2.y, tA1);
                    tA1 = f2fma(apA[3], q3.y, tA1); tA1 = f2fma(apA[4], q4.y, tA1);
                    tA1 = f2fma(apA[5], q5.y, tA1);
                    uint64_t tB1 = f2fma(apB[0], q0.y, bi.y);
                    tB1 = f2fma(apB[1], q1.y, tB1); tB1 = f2fma(apB[2], q2.y, tB1);
                    tB1 = f2fma(apB[3], q3.y, tB1); tB1 = f2fma(apB[4], q4.y, tB1);
                    tB1 = f2fma(apB[5], q5.y, tB1);
                    tA0 = f2relu(tA0); tB0 = f2relu(tB0);
                    tA1 = f2relu(tA1); tB1 = f2relu(tB1);
                    msgA[2 * c + 0] = f2fma(xpA, tA0, msgA[2 * c + 0]);
                    msgA[2 * c + 1] = f2fma(xpA, tA1, msgA[2 * c + 1]);
                    msgB[2 * c + 0] = f2fma(xpB, tB0, msgB[2 * c + 0]);
                    msgB[2 * c + 1] = f2fma(xpB, tB1, msgB[2 * c + 1]);
                }
            };

            if (CIN == 1) {
                const float xiA = vA ? __ldg(xrA) : 0.f;
                const float xiB = vB ? __ldg(xrB) : 0.f;
                body(0, xiA, xiB);
            } else {
                const float4* xA4 = (const float4*)xrA;
                const float4* xB4 = (const float4*)xrB;
#pragma unroll 1   // keep 4-i blocks rolled: I$ discipline
                for (int ib = 0; ib < CIN / 4; ib++) {
                    float4 xqA = make_float4(0.f, 0.f, 0.f, 0.f);
                    float4 xqB = make_float4(0.f, 0.f, 0.f, 0.f);
                    if (vA) xqA = __ldg(xA4 + ib);
                    if (vB) xqB = __ldg(xB4 + ib);
                    body(4 * ib + 0, xqA.x, xqB.x);
                    body(4 * ib + 1, xqA.y, xqB.y);
                    body(4 * ib + 2, xqA.z, xqB.z);
                    body(4 * ib + 3, xqA.w, xqB.w);
                }
            }
        }

        // fold pair accumulators, then block reduction (4 warps)
#pragma unroll
        for (int p = 0; p < SLICEP / 2; p++) {
            float loA, hiA, loB, hiB;
            f2upk(msgA[p], loA, hiA); f2upk(msgB[p], loB, hiB);
            float lo = loA + loB, hi = hiA + hiB;
#pragma unroll
            for (int sh = 16; sh; sh >>= 1) {
                lo += __shfl_down_sync(0xffffffffu, lo, sh);
                hi += __shfl_down_sync(0xffffffffu, hi, sh);
            }
            if ((tid & 31) == 0) {
                atomicAdd(&sacc[2 * p + 0], lo);
                atomicAdd(&sacc[2 * p + 1], hi);
            }
        }
        __syncthreads();

        // finalize this item's output columns
        if (tid < SLICE) {
            const int o = sl * SLICE + tid;
            float r = bias[o];
#pragma unroll 1
            for (int i = 0; i < CIN; i++)
                r = fmaf(hin[d * CIN + i], root[i * COUT + o], r);
            hout[d * COUT + o] = fmaxf(fmaf(sacc[tid], g_invc[d], r), 0.f);
        }
        // next iteration's post-atomic __syncthreads orders finalize vs sacc reset
    }
}

// ---------------- CBT: out[i][j] = sum_k |h[i][k]-h[j][k]|, k<5 --------------
__global__ __launch_bounds__(256) void cbt_kernel(const float* __restrict__ h,
                                                  float* __restrict__ out) {
    __shared__ float sh[N_NODES * 5];
    for (int t = threadIdx.x; t < N_NODES * 5; t += 256) sh[t] = h[t];
    __syncthreads();
    const int i = blockIdx.x;
    const float h0 = sh[i * 5 + 0], h1 = sh[i * 5 + 1], h2 = sh[i * 5 + 2],
                h3 = sh[i * 5 + 3], h4 = sh[i * 5 + 4];
    for (int j = threadIdx.x; j < N_NODES; j += 256) {
        float s = fabsf(h0 - sh[j * 5 + 0]) + fabsf(h1 - sh[j * 5 + 1]) +
                  fabsf(h2 - sh[j * 5 + 2]) + fabsf(h3 - sh[j * 5 + 3]) +
                  fabsf(h4 - sh[j * 5 + 4]);
        out[i * N_NODES + j] = s;
    }
}

// ---------------- launch ------------------------------------------------------
extern "C" void kernel_launch(void* const* d_in, const int* in_sizes, int n_in,
                              void* d_out, int out_size) {
    const float* x    = (const float*)d_in[0];
    const float* ea   = (const float*)d_in[1];
    const int*   ei   = (const int*)d_in[2];
    const float* We1  = (const float*)d_in[3];
    const float* be1  = (const float*)d_in[4];
    const float* root1= (const float*)d_in[5];
    const float* b1   = (const float*)d_in[6];
    const float* We2  = (const float*)d_in[7];
    const float* be2  = (const float*)d_in[8];
    const float* root2= (const float*)d_in[9];
    const float* b2   = (const float*)d_in[10];
    const float* We3  = (const float*)d_in[11];
    const float* be3  = (const float*)d_in[12];
    const float* root3= (const float*)d_in[13];
    const float* b3   = (const float*)d_in[14];
    float* out = (float*)d_out;

    const int* src = ei;
    const int* dst = ei + N_EDGES;

    float* hA = nullptr;
    float* hB = nullptr;
    cudaGetSymbolAddress((void**)&hA, g_bufA);
    cudaGetSymbolAddress((void**)&hB, g_bufB);

    // CSR build + edge-data permute (src folded into padded ea row);
    // plan_kernel also resets the work-stealing counters every launch.
    count_kernel<<<CHUNKS, 256>>>(dst);
    plan_kernel<<<1, N_NODES>>>();
    scatter_kernel<<<CHUNKS, 256>>>(src, dst, ea);

    // persistent work-stealing layers (all CTAs resident, no waves, no tail)
    layer_persist<1, 36, 2, 18, 20><<<PGRID, NT>>>(We1, be1, root1, b1, x,  hA, 0);
    layer_persist<36, 24, 2, 12, 12><<<PGRID, NT>>>(We2, be2, root2, b2, hA, hB, 1);
    layer_persist<24, 5, 1, 5, 8><<<PGRID, NT>>>(We3, be3, root3, b3, hB, hA, 2);

    cbt_kernel<<<N_NODES, 256>>>(hA, out);
}